// round 1
// baseline (speedup 1.0000x reference)
#include <cuda_runtime.h>
#include <math.h>

#define NN      50000
#define INDIM   512
#define HID     256
#define CC      8
#define EHID    64
#define E2C     400000
#define EEC     800000
#define T_ITERS 10
#define ETA_C   0.2f
#define W_MAXC  0.8f
#define ALPHA_MAXC 1.5f
#define EPS_C   1e-12f

// ------------------- scratch (device globals; no allocation allowed) ---------
__device__ __align__(16) float g_h[NN * HID];        // 51.2 MB
__device__ __align__(16) float g_logphi[NN * CC];
__device__ __align__(16) float g_deg[NN];
__device__ __align__(16) float g_logdeg[NN];
__device__ __align__(16) float g_w[E2C];
__device__ __align__(16) float g_en[E2C];
__device__ __align__(16) float g_m[EEC * CC];        // 25.6 MB
__device__ __align__(16) float g_lf[EEC * CC];       // 25.6 MB
__device__ __align__(16) float g_sum[NN * CC];
__device__ __align__(16) float g_Rs[64];
__device__ float g_alpha;

// ------------------- small prep: symmetrized/scaled R and alpha --------------
__global__ void prep_R_k(const float* __restrict__ R_raw,
                         const float* __restrict__ rsl,
                         const float* __restrict__ msg) {
    int t = threadIdx.x;
    if (t == 0) g_alpha = ALPHA_MAXC / (1.f + expf(-msg[0]));
    if (t < 64) {
        int c = t >> 3, d = t & 7;
        float r = 0.5f * (R_raw[c * 8 + d] + R_raw[d * 8 + c]);
        float xr = rsl[0];
        float sp = (xr > 20.f) ? xr : log1pf(expf(xr));
        g_Rs[t] = (sp + 1e-6f) * tanhf(r);
    }
}

// ------------------- encoder GEMM: h = relu(x @ W1 + b1) ---------------------
// block: 128 rows x 64 cols, 256 threads, 8x4 micro-tile
__global__ __launch_bounds__(256) void enc_gemm_k(const float* __restrict__ X,
                                                  const float* __restrict__ W,
                                                  const float* __restrict__ B) {
    __shared__ float Xs[16][137];
    __shared__ float Ws[16][64];
    int tid = threadIdx.x;
    int tx = tid & 15, ty = tid >> 4;
    int row0 = blockIdx.x * 128;
    int col0 = blockIdx.y * 64;
    float acc[8][4];
#pragma unroll
    for (int j = 0; j < 8; j++)
#pragma unroll
        for (int u = 0; u < 4; u++) acc[j][u] = 0.f;

    for (int k0 = 0; k0 < INDIM; k0 += 16) {
#pragma unroll
        for (int i = 0; i < 2; i++) {
            int m = (tid >> 2) + i * 64;
            int k4 = (tid & 3) * 4;
            int gr = row0 + m;
            float4 v = make_float4(0.f, 0.f, 0.f, 0.f);
            if (gr < NN) v = *(const float4*)(X + (size_t)gr * INDIM + k0 + k4);
            Xs[k4 + 0][m] = v.x; Xs[k4 + 1][m] = v.y;
            Xs[k4 + 2][m] = v.z; Xs[k4 + 3][m] = v.w;
        }
        {
            int k = tid >> 4;
            int c4 = (tid & 15) * 4;
            *(float4*)&Ws[k][c4] = *(const float4*)(W + (size_t)(k0 + k) * HID + col0 + c4);
        }
        __syncthreads();
#pragma unroll
        for (int kk = 0; kk < 16; kk++) {
            float a[8];
#pragma unroll
            for (int j = 0; j < 8; j++) a[j] = Xs[kk][ty * 8 + j];
            float4 w4 = *(float4*)&Ws[kk][tx * 4];
#pragma unroll
            for (int j = 0; j < 8; j++) {
                acc[j][0] += a[j] * w4.x;
                acc[j][1] += a[j] * w4.y;
                acc[j][2] += a[j] * w4.z;
                acc[j][3] += a[j] * w4.w;
            }
        }
        __syncthreads();
    }
    float4 b4 = *(const float4*)(B + col0 + tx * 4);
#pragma unroll
    for (int j = 0; j < 8; j++) {
        int gr = row0 + ty * 8 + j;
        if (gr < NN) {
            float4 o;
            o.x = fmaxf(acc[j][0] + b4.x, 0.f);
            o.y = fmaxf(acc[j][1] + b4.y, 0.f);
            o.z = fmaxf(acc[j][2] + b4.z, 0.f);
            o.w = fmaxf(acc[j][3] + b4.w, 0.f);
            *(float4*)(g_h + (size_t)gr * HID + col0 + tx * 4) = o;
        }
    }
}

// ------------------- logits + log_softmax: one warp per node ------------------
__global__ void logits_k(const float* __restrict__ W2, const float* __restrict__ B2) {
    int gt = blockIdx.x * blockDim.x + threadIdx.x;
    int node = gt >> 5, lane = gt & 31;
    if (node >= NN) return;
    const float* hrow = g_h + (size_t)node * HID;
    float acc[8];
#pragma unroll
    for (int c = 0; c < 8; c++) acc[c] = 0.f;
    for (int j = lane; j < HID; j += 32) {
        float hv = hrow[j];
        float4 wA = *(const float4*)(W2 + j * 8);
        float4 wB = *(const float4*)(W2 + j * 8 + 4);
        acc[0] += hv * wA.x; acc[1] += hv * wA.y;
        acc[2] += hv * wA.z; acc[3] += hv * wA.w;
        acc[4] += hv * wB.x; acc[5] += hv * wB.y;
        acc[6] += hv * wB.z; acc[7] += hv * wB.w;
    }
#pragma unroll
    for (int c = 0; c < 8; c++)
#pragma unroll
        for (int off = 16; off; off >>= 1)
            acc[c] += __shfl_xor_sync(0xffffffffu, acc[c], off);
    if (lane == 0) {
        float lg[8], mx = -1e30f;
#pragma unroll
        for (int c = 0; c < 8; c++) { lg[c] = acc[c] + B2[c]; mx = fmaxf(mx, lg[c]); }
        float s = 0.f;
#pragma unroll
        for (int c = 0; c < 8; c++) s += expf(lg[c] - mx);
        float lse = mx + logf(s);
        float4 o0 = make_float4(lg[0] - lse, lg[1] - lse, lg[2] - lse, lg[3] - lse);
        float4 o1 = make_float4(lg[4] - lse, lg[5] - lse, lg[6] - lse, lg[7] - lse);
        *(float4*)(g_logphi + node * 8) = o0;
        *(float4*)(g_logphi + node * 8 + 4) = o1;
    }
}

// ------------------- degrees -------------------------------------------------
__global__ void zero_deg_k() {
    int i = blockIdx.x * blockDim.x + threadIdx.x;
    if (i < NN) g_deg[i] = 0.f;
}
__global__ void deg_k(const int* __restrict__ src, const int* __restrict__ dst) {
    int e = blockIdx.x * blockDim.x + threadIdx.x;
    if (e >= E2C) return;
    atomicAdd(&g_deg[src[e]], 1.f);
    atomicAdd(&g_deg[dst[e]], 1.f);
}
__global__ void logdeg_k() {
    int n = blockIdx.x * blockDim.x + threadIdx.x;
    if (n < NN) g_logdeg[n] = logf(g_deg[n] + 1.f);
}

// ------------------- edge MLP (only E2 unique edges; reverse is identical) ----
// block: 128 edges x 64 hidden units, 256 threads, 8x4 micro-tile
__global__ __launch_bounds__(256) void edge_mlp_k(const int* __restrict__ src,
                                                  const int* __restrict__ dst,
                                                  const float* __restrict__ W1,
                                                  const float* __restrict__ B1,
                                                  const float* __restrict__ W2,
                                                  const float* __restrict__ B2) {
    __shared__ int   ss[128], dd[128];
    __shared__ float s0s[128], s1s[128];
    __shared__ float Hs[16][137], Hd[16][137];
    __shared__ float Was[16][64], Wbs[16][64];
    __shared__ float Wg0[64], Wg1[64], b1s[64], w2s[64];
    int tid = threadIdx.x;
    int e0 = blockIdx.x * 128;

    if (tid < 128) {
        int ge = e0 + tid;
        int s = src[ge], d = dst[ge];
        ss[tid] = s; dd[tid] = d;
        float a = g_logdeg[s], b = g_logdeg[d];
        s0s[tid] = a + b; s1s[tid] = fabsf(a - b);
        float ds = fmaxf(g_deg[s], 1.f), dd2 = fmaxf(g_deg[d], 1.f);
        g_en[ge] = rsqrtf(ds * dd2);
    } else {
        int t = tid - 128;
        if (t < 64) { Wg0[t] = W1[512 * 64 + t]; b1s[t] = B1[t]; }
        else { int u = t - 64; Wg1[u] = W1[513 * 64 + u]; w2s[u] = W2[u]; }
    }
    __syncthreads();

    int tx = tid & 15, ty = tid >> 4;
    float acc[8][4];
#pragma unroll
    for (int j = 0; j < 8; j++)
#pragma unroll
        for (int u = 0; u < 4; u++) acc[j][u] = 0.f;

    for (int f0 = 0; f0 < HID; f0 += 16) {
#pragma unroll
        for (int i = 0; i < 2; i++) {
            int idx = tid + i * 256;
            int e = idx >> 2;
            int f4 = (idx & 3) * 4;
            float4 v = *(const float4*)(g_h + (size_t)ss[e] * HID + f0 + f4);
            Hs[f4 + 0][e] = v.x; Hs[f4 + 1][e] = v.y;
            Hs[f4 + 2][e] = v.z; Hs[f4 + 3][e] = v.w;
            float4 u = *(const float4*)(g_h + (size_t)dd[e] * HID + f0 + f4);
            Hd[f4 + 0][e] = u.x; Hd[f4 + 1][e] = u.y;
            Hd[f4 + 2][e] = u.z; Hd[f4 + 3][e] = u.w;
        }
        {
            int f = tid >> 4;
            int c4 = (tid & 15) * 4;
            *(float4*)&Was[f][c4] = *(const float4*)(W1 + (size_t)(f0 + f) * 64 + c4);
            *(float4*)&Wbs[f][c4] = *(const float4*)(W1 + (size_t)(256 + f0 + f) * 64 + c4);
        }
        __syncthreads();
#pragma unroll
        for (int f = 0; f < 16; f++) {
            float p[8], q[8];
#pragma unroll
            for (int j = 0; j < 8; j++) {
                float a = Hs[f][ty * 8 + j], b = Hd[f][ty * 8 + j];
                p[j] = a * b; q[j] = fabsf(a - b);
            }
            float4 wa = *(float4*)&Was[f][tx * 4];
            float4 wb = *(float4*)&Wbs[f][tx * 4];
#pragma unroll
            for (int j = 0; j < 8; j++) {
                acc[j][0] += p[j] * wa.x; acc[j][0] += q[j] * wb.x;
                acc[j][1] += p[j] * wa.y; acc[j][1] += q[j] * wb.y;
                acc[j][2] += p[j] * wa.z; acc[j][2] += q[j] * wb.z;
                acc[j][3] += p[j] * wa.w; acc[j][3] += q[j] * wb.w;
            }
        }
        __syncthreads();
    }
    // epilogue: struct features + bias + relu + w2 contraction + sigmoid
    float B2v = B2[0];
#pragma unroll
    for (int j = 0; j < 8; j++) {
        int e = ty * 8 + j;
        float s0 = s0s[e], s1 = s1s[e];
        float sum = 0.f;
#pragma unroll
        for (int u4 = 0; u4 < 4; u4++) {
            int u = tx * 4 + u4;
            float v = acc[j][u4] + s0 * Wg0[u] + s1 * Wg1[u] + b1s[u];
            v = fmaxf(v, 0.f);
            sum += v * w2s[u];
        }
#pragma unroll
        for (int off = 8; off; off >>= 1)
            sum += __shfl_down_sync(0xffffffffu, sum, off, 16);
        if (tx == 0) {
            float wr = sum + B2v;
            g_w[e0 + e] = W_MAXC / (1.f + expf(-wr));
        }
    }
}

// ------------------- init m = softmax(log_phi[src]) over all E edges ----------
__global__ void init_m_k(const int* __restrict__ srcAll) {
    int e = blockIdx.x * blockDim.x + threadIdx.x;
    if (e >= EEC) return;
    int s = srcAll[e];
    float4 A = *(const float4*)(g_logphi + s * 8);
    float4 Bv = *(const float4*)(g_logphi + s * 8 + 4);
    float lp[8] = {A.x, A.y, A.z, A.w, Bv.x, Bv.y, Bv.z, Bv.w};
    float mx = -1e30f;
#pragma unroll
    for (int c = 0; c < 8; c++) mx = fmaxf(mx, lp[c]);
    float ex[8], sm = 0.f;
#pragma unroll
    for (int c = 0; c < 8; c++) { ex[c] = expf(lp[c] - mx); sm += ex[c]; }
    float inv = 1.f / sm;
    float4 o0 = make_float4(ex[0] * inv, ex[1] * inv, ex[2] * inv, ex[3] * inv);
    float4 o1 = make_float4(ex[4] * inv, ex[5] * inv, ex[6] * inv, ex[7] * inv);
    *(float4*)(g_m + (size_t)e * 8) = o0;
    *(float4*)(g_m + (size_t)e * 8 + 4) = o1;
}

__global__ void zero_sum_k() {
    int i = blockIdx.x * blockDim.x + threadIdx.x;
    if (i < NN * CC) g_sum[i] = 0.f;
}

// ------------------- BP iteration A: per edge-pair, K recomputed on the fly ---
__global__ __launch_bounds__(256) void iterA_k(const int* __restrict__ src,
                                               const int* __restrict__ dst) {
    __shared__ float Rs[64];
    if (threadIdx.x < 64) Rs[threadIdx.x] = g_Rs[threadIdx.x];
    __syncthreads();
    int e = blockIdx.x * blockDim.x + threadIdx.x;
    if (e >= E2C) return;
    float w = g_w[e], en = g_en[e];
    int s = src[e], d = dst[e];
    float4 a0 = *(const float4*)(g_m + (size_t)e * 8);
    float4 a1 = *(const float4*)(g_m + (size_t)e * 8 + 4);
    float4 b0 = *(const float4*)(g_m + (size_t)(e + E2C) * 8);
    float4 b1 = *(const float4*)(g_m + (size_t)(e + E2C) * 8 + 4);
    float m1[8] = {a0.x, a0.y, a0.z, a0.w, a1.x, a1.y, a1.z, a1.w};
    float m2[8] = {b0.x, b0.y, b0.z, b0.w, b1.x, b1.y, b1.z, b1.w};
    float f1[8], f2[8];
#pragma unroll
    for (int c = 0; c < 8; c++) { f1[c] = 0.f; f2[c] = 0.f; }
#pragma unroll
    for (int c = 0; c < 8; c++) {
        float mc1 = m1[c], mc2 = m2[c];
#pragma unroll
        for (int dd2 = 0; dd2 < 8; dd2++) {
            float k = __expf(w * Rs[c * 8 + dd2]);
            f1[dd2] += mc1 * k;
            f2[dd2] += mc2 * k;
        }
    }
    float lf1[8], lf2[8];
#pragma unroll
    for (int c = 0; c < 8; c++) {
        lf1[c] = __logf(fmaxf(f1[c], EPS_C)) * en;
        lf2[c] = __logf(fmaxf(f2[c], EPS_C)) * en;
    }
    *(float4*)(g_lf + (size_t)e * 8)     = make_float4(lf1[0], lf1[1], lf1[2], lf1[3]);
    *(float4*)(g_lf + (size_t)e * 8 + 4) = make_float4(lf1[4], lf1[5], lf1[6], lf1[7]);
    *(float4*)(g_lf + (size_t)(e + E2C) * 8)     = make_float4(lf2[0], lf2[1], lf2[2], lf2[3]);
    *(float4*)(g_lf + (size_t)(e + E2C) * 8 + 4) = make_float4(lf2[4], lf2[5], lf2[6], lf2[7]);
#pragma unroll
    for (int c = 0; c < 8; c++) {
        atomicAdd(&g_sum[d * 8 + c], lf1[c]);
        atomicAdd(&g_sum[s * 8 + c], lf2[c]);
    }
}

// ------------------- BP iteration B: message update ---------------------------
__device__ __forceinline__ void upd_m(float* mrow, const float* lp, const float* si,
                                      const float* lf_rev, float alpha) {
    float t[8], mx = -1e30f;
#pragma unroll
    for (int c = 0; c < 8; c++) { t[c] = lp[c] + alpha * (si[c] - lf_rev[c]); mx = fmaxf(mx, t[c]); }
    float ex[8], sm = 0.f;
#pragma unroll
    for (int c = 0; c < 8; c++) { ex[c] = __expf(t[c] - mx); sm += ex[c]; }
    float inv = 1.f / sm;
    float m[8], tot = 0.f;
#pragma unroll
    for (int c = 0; c < 8; c++) {
        m[c] = (1.f - ETA_C) * mrow[c] + ETA_C * (ex[c] * inv);
        m[c] = fmaxf(m[c], EPS_C);
        tot += m[c];
    }
    float it = 1.f / tot;
#pragma unroll
    for (int c = 0; c < 8; c++) mrow[c] = m[c] * it;
}

__global__ __launch_bounds__(256) void iterB_k(const int* __restrict__ src,
                                               const int* __restrict__ dst) {
    int e = blockIdx.x * blockDim.x + threadIdx.x;
    if (e >= E2C) return;
    float alpha = g_alpha;
    int s = src[e], d = dst[e];
    float lf1[8], lf2[8], sis[8], sid[8], lps[8], lpd[8], m1[8], m2[8];
    {
        float4 v0 = *(const float4*)(g_lf + (size_t)e * 8);
        float4 v1 = *(const float4*)(g_lf + (size_t)e * 8 + 4);
        lf1[0]=v0.x; lf1[1]=v0.y; lf1[2]=v0.z; lf1[3]=v0.w;
        lf1[4]=v1.x; lf1[5]=v1.y; lf1[6]=v1.z; lf1[7]=v1.w;
        v0 = *(const float4*)(g_lf + (size_t)(e + E2C) * 8);
        v1 = *(const float4*)(g_lf + (size_t)(e + E2C) * 8 + 4);
        lf2[0]=v0.x; lf2[1]=v0.y; lf2[2]=v0.z; lf2[3]=v0.w;
        lf2[4]=v1.x; lf2[5]=v1.y; lf2[6]=v1.z; lf2[7]=v1.w;
        v0 = *(const float4*)(g_sum + s * 8); v1 = *(const float4*)(g_sum + s * 8 + 4);
        sis[0]=v0.x; sis[1]=v0.y; sis[2]=v0.z; sis[3]=v0.w;
        sis[4]=v1.x; sis[5]=v1.y; sis[6]=v1.z; sis[7]=v1.w;
        v0 = *(const float4*)(g_sum + d * 8); v1 = *(const float4*)(g_sum + d * 8 + 4);
        sid[0]=v0.x; sid[1]=v0.y; sid[2]=v0.z; sid[3]=v0.w;
        sid[4]=v1.x; sid[5]=v1.y; sid[6]=v1.z; sid[7]=v1.w;
        v0 = *(const float4*)(g_logphi + s * 8); v1 = *(const float4*)(g_logphi + s * 8 + 4);
        lps[0]=v0.x; lps[1]=v0.y; lps[2]=v0.z; lps[3]=v0.w;
        lps[4]=v1.x; lps[5]=v1.y; lps[6]=v1.z; lps[7]=v1.w;
        v0 = *(const float4*)(g_logphi + d * 8); v1 = *(const float4*)(g_logphi + d * 8 + 4);
        lpd[0]=v0.x; lpd[1]=v0.y; lpd[2]=v0.z; lpd[3]=v0.w;
        lpd[4]=v1.x; lpd[5]=v1.y; lpd[6]=v1.z; lpd[7]=v1.w;
        v0 = *(const float4*)(g_m + (size_t)e * 8); v1 = *(const float4*)(g_m + (size_t)e * 8 + 4);
        m1[0]=v0.x; m1[1]=v0.y; m1[2]=v0.z; m1[3]=v0.w;
        m1[4]=v1.x; m1[5]=v1.y; m1[6]=v1.z; m1[7]=v1.w;
        v0 = *(const float4*)(g_m + (size_t)(e + E2C) * 8); v1 = *(const float4*)(g_m + (size_t)(e + E2C) * 8 + 4);
        m2[0]=v0.x; m2[1]=v0.y; m2[2]=v0.z; m2[3]=v0.w;
        m2[4]=v1.x; m2[5]=v1.y; m2[6]=v1.z; m2[7]=v1.w;
    }
    // edge e (s->d): excl = sum_in[s] - lf[rev] = sis - lf2 ; lp_src = lps
    upd_m(m1, lps, sis, lf2, alpha);
    // edge e+E2 (d->s): excl = sum_in[d] - lf1 ; lp_src = lpd
    upd_m(m2, lpd, sid, lf1, alpha);
    *(float4*)(g_m + (size_t)e * 8)     = make_float4(m1[0], m1[1], m1[2], m1[3]);
    *(float4*)(g_m + (size_t)e * 8 + 4) = make_float4(m1[4], m1[5], m1[6], m1[7]);
    *(float4*)(g_m + (size_t)(e + E2C) * 8)     = make_float4(m2[0], m2[1], m2[2], m2[3]);
    *(float4*)(g_m + (size_t)(e + E2C) * 8 + 4) = make_float4(m2[4], m2[5], m2[6], m2[7]);
}

// ------------------- final beliefs -------------------------------------------
__global__ void beliefs_k(float* __restrict__ out) {
    int n = blockIdx.x * blockDim.x + threadIdx.x;
    if (n >= NN) return;
    float alpha = g_alpha;
    float4 l0 = *(const float4*)(g_logphi + n * 8);
    float4 l1 = *(const float4*)(g_logphi + n * 8 + 4);
    float4 s0 = *(const float4*)(g_sum + n * 8);
    float4 s1 = *(const float4*)(g_sum + n * 8 + 4);
    float t[8] = {l0.x + alpha * s0.x, l0.y + alpha * s0.y,
                  l0.z + alpha * s0.z, l0.w + alpha * s0.w,
                  l1.x + alpha * s1.x, l1.y + alpha * s1.y,
                  l1.z + alpha * s1.z, l1.w + alpha * s1.w};
    float mx = -1e30f;
#pragma unroll
    for (int c = 0; c < 8; c++) mx = fmaxf(mx, t[c]);
    float ex[8], sm = 0.f;
#pragma unroll
    for (int c = 0; c < 8; c++) { ex[c] = expf(t[c] - mx); sm += ex[c]; }
    float inv = 1.f / sm;
    *(float4*)(out + (size_t)n * 8)     = make_float4(ex[0]*inv, ex[1]*inv, ex[2]*inv, ex[3]*inv);
    *(float4*)(out + (size_t)n * 8 + 4) = make_float4(ex[4]*inv, ex[5]*inv, ex[6]*inv, ex[7]*inv);
}

// ------------------- launcher -------------------------------------------------
extern "C" void kernel_launch(void* const* d_in, const int* in_sizes, int n_in,
                              void* d_out, int out_size) {
    const float* x      = (const float*)d_in[0];
    const int*   ei     = (const int*)  d_in[1];   // [2, E] : row0 src, row1 dst
    const float* enc_w1 = (const float*)d_in[3];
    const float* enc_b1 = (const float*)d_in[4];
    const float* enc_w2 = (const float*)d_in[5];
    const float* enc_b2 = (const float*)d_in[6];
    const float* edge_w1= (const float*)d_in[7];
    const float* edge_b1= (const float*)d_in[8];
    const float* edge_w2= (const float*)d_in[9];
    const float* edge_b2= (const float*)d_in[10];
    const float* R_raw  = (const float*)d_in[11];
    const float* rsl    = (const float*)d_in[12];
    const float* msg    = (const float*)d_in[13];
    float* out = (float*)d_out;

    const int* src = ei;         // first E entries
    const int* dst = ei + EEC;   // second row

    prep_R_k<<<1, 64>>>(R_raw, rsl, msg);
    enc_gemm_k<<<dim3((NN + 127) / 128, HID / 64), 256>>>(x, enc_w1, enc_b1);
    logits_k<<<(NN * 32 + 255) / 256, 256>>>(enc_w2, enc_b2);
    zero_deg_k<<<(NN + 255) / 256, 256>>>();
    deg_k<<<(E2C + 255) / 256, 256>>>(src, dst);
    logdeg_k<<<(NN + 255) / 256, 256>>>();
    edge_mlp_k<<<E2C / 128, 256>>>(src, dst, edge_w1, edge_b1, edge_w2, edge_b2);
    init_m_k<<<(EEC + 255) / 256, 256>>>(src);  // src row spans all E directed edges

    for (int t = 0; t < T_ITERS; t++) {
        zero_sum_k<<<(NN * CC + 255) / 256, 256>>>();
        iterA_k<<<(E2C + 255) / 256, 256>>>(src, dst);
        iterB_k<<<(E2C + 255) / 256, 256>>>(src, dst);
    }
    zero_sum_k<<<(NN * CC + 255) / 256, 256>>>();
    iterA_k<<<(E2C + 255) / 256, 256>>>(src, dst);
    beliefs_k<<<(NN + 255) / 256, 256>>>(out);
}

// round 2
// speedup vs baseline: 1.2029x; 1.2029x over previous
#include <cuda_runtime.h>
#include <math.h>

#define NN      50000
#define INDIM   512
#define HID     256
#define CC      8
#define E2C     400000
#define EEC     800000
#define T_ITERS 10
#define ETA_C   0.2f
#define W_MAXC  0.8f
#define ALPHA_MAXC 1.5f
#define EPS_C   1e-12f

// ------------------- scratch (device globals; no allocation allowed) ---------
__device__ __align__(16) float g_h[NN * HID];        // 51.2 MB
__device__ __align__(16) float g_logphi[NN * CC];
__device__ __align__(16) float g_deg[NN];
__device__ __align__(16) float g_logdeg[NN];
__device__ __align__(16) float g_w[E2C];
__device__ __align__(16) float g_en[E2C];
__device__ __align__(16) float g_m[EEC * CC];        // 25.6 MB
__device__ __align__(16) float g_lf[EEC * CC];       // 25.6 MB
__device__ __align__(16) float g_sumA[NN * CC];
__device__ __align__(16) float g_sumB[NN * CC];
__device__ __align__(16) float g_Rs[64];
__device__ float g_alpha;

// ------------------- packed f32x2 FMA ----------------------------------------
union F2 { float2 f; unsigned long long u; };

__device__ __forceinline__ void ffma2(F2& d, const F2& a, const F2& b) {
    asm("fma.rn.f32x2 %0, %1, %2, %0;" : "+l"(d.u) : "l"(a.u), "l"(b.u));
}
__device__ __forceinline__ F2 bcast2(float v) {
    F2 r; r.f = make_float2(v, v); return r;
}

// ------------------- generic zero --------------------------------------------
__global__ void zero4_k(float4* __restrict__ p, int n4) {
    int i = blockIdx.x * blockDim.x + threadIdx.x;
    if (i < n4) p[i] = make_float4(0.f, 0.f, 0.f, 0.f);
}

// ------------------- small prep: symmetrized/scaled R and alpha --------------
__global__ void prep_R_k(const float* __restrict__ R_raw,
                         const float* __restrict__ rsl,
                         const float* __restrict__ msg) {
    int t = threadIdx.x;
    if (t == 0) g_alpha = ALPHA_MAXC / (1.f + expf(-msg[0]));
    if (t < 64) {
        int c = t >> 3, d = t & 7;
        float r = 0.5f * (R_raw[c * 8 + d] + R_raw[d * 8 + c]);
        float xr = rsl[0];
        float sp = (xr > 20.f) ? xr : log1pf(expf(xr));
        g_Rs[t] = (sp + 1e-6f) * tanhf(r);
    }
}

// ------------------- encoder GEMM: h = relu(x @ W1 + b1) ---------------------
// block: 128 rows x 64 cols, 256 threads, (4 row-pairs)x(4 cols) FFMA2 micro-tile
__global__ __launch_bounds__(256) void enc_gemm_k(const float* __restrict__ X,
                                                  const float* __restrict__ W,
                                                  const float* __restrict__ B) {
    __shared__ float Xs[16][138];
    __shared__ float Ws[16][64];
    int tid = threadIdx.x;
    int tx = tid & 15, ty = tid >> 4;
    int row0 = blockIdx.x * 128;
    int col0 = blockIdx.y * 64;
    F2 acc[4][4];
#pragma unroll
    for (int jp = 0; jp < 4; jp++)
#pragma unroll
        for (int u = 0; u < 4; u++) acc[jp][u].f = make_float2(0.f, 0.f);

    for (int k0 = 0; k0 < INDIM; k0 += 16) {
#pragma unroll
        for (int i = 0; i < 2; i++) {
            int m = (tid >> 2) + i * 64;
            int k4 = (tid & 3) * 4;
            int gr = row0 + m;
            float4 v = make_float4(0.f, 0.f, 0.f, 0.f);
            if (gr < NN) v = *(const float4*)(X + (size_t)gr * INDIM + k0 + k4);
            Xs[k4 + 0][m] = v.x; Xs[k4 + 1][m] = v.y;
            Xs[k4 + 2][m] = v.z; Xs[k4 + 3][m] = v.w;
        }
        {
            int k = tid >> 4;
            int c4 = (tid & 15) * 4;
            *(float4*)&Ws[k][c4] = *(const float4*)(W + (size_t)(k0 + k) * HID + col0 + c4);
        }
        __syncthreads();
#pragma unroll
        for (int kk = 0; kk < 16; kk++) {
            F2 a2[4];
#pragma unroll
            for (int jp = 0; jp < 4; jp++)
                a2[jp].f = *(const float2*)&Xs[kk][ty * 8 + jp * 2];
            float4 w4 = *(const float4*)&Ws[kk][tx * 4];
            F2 wp[4] = {bcast2(w4.x), bcast2(w4.y), bcast2(w4.z), bcast2(w4.w)};
#pragma unroll
            for (int jp = 0; jp < 4; jp++)
#pragma unroll
                for (int u = 0; u < 4; u++)
                    ffma2(acc[jp][u], a2[jp], wp[u]);
        }
        __syncthreads();
    }
    float4 b4 = *(const float4*)(B + col0 + tx * 4);
#pragma unroll
    for (int jp = 0; jp < 4; jp++) {
#pragma unroll
        for (int h = 0; h < 2; h++) {
            int gr = row0 + ty * 8 + jp * 2 + h;
            if (gr < NN) {
                float4 o;
                float v0 = h ? acc[jp][0].f.y : acc[jp][0].f.x;
                float v1 = h ? acc[jp][1].f.y : acc[jp][1].f.x;
                float v2 = h ? acc[jp][2].f.y : acc[jp][2].f.x;
                float v3 = h ? acc[jp][3].f.y : acc[jp][3].f.x;
                o.x = fmaxf(v0 + b4.x, 0.f);
                o.y = fmaxf(v1 + b4.y, 0.f);
                o.z = fmaxf(v2 + b4.z, 0.f);
                o.w = fmaxf(v3 + b4.w, 0.f);
                *(float4*)(g_h + (size_t)gr * HID + col0 + tx * 4) = o;
            }
        }
    }
}

// ------------------- logits + log_softmax: one warp per node ------------------
__global__ void logits_k(const float* __restrict__ W2, const float* __restrict__ B2) {
    int gt = blockIdx.x * blockDim.x + threadIdx.x;
    int node = gt >> 5, lane = gt & 31;
    if (node >= NN) return;
    const float* hrow = g_h + (size_t)node * HID;
    float acc[8];
#pragma unroll
    for (int c = 0; c < 8; c++) acc[c] = 0.f;
    for (int j = lane; j < HID; j += 32) {
        float hv = hrow[j];
        float4 wA = *(const float4*)(W2 + j * 8);
        float4 wB = *(const float4*)(W2 + j * 8 + 4);
        acc[0] += hv * wA.x; acc[1] += hv * wA.y;
        acc[2] += hv * wA.z; acc[3] += hv * wA.w;
        acc[4] += hv * wB.x; acc[5] += hv * wB.y;
        acc[6] += hv * wB.z; acc[7] += hv * wB.w;
    }
#pragma unroll
    for (int c = 0; c < 8; c++)
#pragma unroll
        for (int off = 16; off; off >>= 1)
            acc[c] += __shfl_xor_sync(0xffffffffu, acc[c], off);
    if (lane == 0) {
        float lg[8], mx = -1e30f;
#pragma unroll
        for (int c = 0; c < 8; c++) { lg[c] = acc[c] + B2[c]; mx = fmaxf(mx, lg[c]); }
        float s = 0.f;
#pragma unroll
        for (int c = 0; c < 8; c++) s += expf(lg[c] - mx);
        float lse = mx + logf(s);
        float4 o0 = make_float4(lg[0] - lse, lg[1] - lse, lg[2] - lse, lg[3] - lse);
        float4 o1 = make_float4(lg[4] - lse, lg[5] - lse, lg[6] - lse, lg[7] - lse);
        *(float4*)(g_logphi + node * 8) = o0;
        *(float4*)(g_logphi + node * 8 + 4) = o1;
    }
}

// ------------------- degrees -------------------------------------------------
__global__ void deg_k(const int* __restrict__ src, const int* __restrict__ dst) {
    int e = blockIdx.x * blockDim.x + threadIdx.x;
    if (e >= E2C) return;
    atomicAdd(&g_deg[src[e]], 1.f);
    atomicAdd(&g_deg[dst[e]], 1.f);
}
__global__ void logdeg_k() {
    int n = blockIdx.x * blockDim.x + threadIdx.x;
    if (n < NN) g_logdeg[n] = logf(g_deg[n] + 1.f);
}

// ------------------- edge MLP (only E2 unique edges; reverse is identical) ----
// block: 128 edges x 64 hidden units; P/Q staged in shared; FFMA2 micro-tile
__global__ __launch_bounds__(256) void edge_mlp_k(const int* __restrict__ src,
                                                  const int* __restrict__ dst,
                                                  const float* __restrict__ W1,
                                                  const float* __restrict__ B1,
                                                  const float* __restrict__ W2,
                                                  const float* __restrict__ B2) {
    __shared__ int   ss[128], dd[128];
    __shared__ float s0s[128], s1s[128];
    __shared__ float Ps[16][138], Qs[16][138];
    __shared__ float Was[16][64], Wbs[16][64];
    __shared__ float Wg0[64], Wg1[64], b1s[64], w2s[64];
    int tid = threadIdx.x;
    int e0 = blockIdx.x * 128;

    if (tid < 128) {
        int ge = e0 + tid;
        int s = src[ge], d = dst[ge];
        ss[tid] = s; dd[tid] = d;
        float a = g_logdeg[s], b = g_logdeg[d];
        s0s[tid] = a + b; s1s[tid] = fabsf(a - b);
        float ds = fmaxf(g_deg[s], 1.f), dd2 = fmaxf(g_deg[d], 1.f);
        g_en[ge] = rsqrtf(ds * dd2);
    } else {
        int t = tid - 128;
        if (t < 64) { Wg0[t] = W1[512 * 64 + t]; b1s[t] = B1[t]; }
        else { int u = t - 64; Wg1[u] = W1[513 * 64 + u]; w2s[u] = W2[u]; }
    }
    __syncthreads();

    int tx = tid & 15, ty = tid >> 4;
    F2 acc[4][4];
#pragma unroll
    for (int jp = 0; jp < 4; jp++)
#pragma unroll
        for (int u = 0; u < 4; u++) acc[jp][u].f = make_float2(0.f, 0.f);

    for (int f0 = 0; f0 < HID; f0 += 16) {
#pragma unroll
        for (int i = 0; i < 2; i++) {
            int idx = tid + i * 256;
            int e = idx >> 2;
            int f4 = (idx & 3) * 4;
            float4 v = *(const float4*)(g_h + (size_t)ss[e] * HID + f0 + f4);
            float4 u = *(const float4*)(g_h + (size_t)dd[e] * HID + f0 + f4);
            Ps[f4 + 0][e] = v.x * u.x; Qs[f4 + 0][e] = fabsf(v.x - u.x);
            Ps[f4 + 1][e] = v.y * u.y; Qs[f4 + 1][e] = fabsf(v.y - u.y);
            Ps[f4 + 2][e] = v.z * u.z; Qs[f4 + 2][e] = fabsf(v.z - u.z);
            Ps[f4 + 3][e] = v.w * u.w; Qs[f4 + 3][e] = fabsf(v.w - u.w);
        }
        {
            int f = tid >> 4;
            int c4 = (tid & 15) * 4;
            *(float4*)&Was[f][c4] = *(const float4*)(W1 + (size_t)(f0 + f) * 64 + c4);
            *(float4*)&Wbs[f][c4] = *(const float4*)(W1 + (size_t)(256 + f0 + f) * 64 + c4);
        }
        __syncthreads();
#pragma unroll
        for (int f = 0; f < 16; f++) {
            F2 p2[4], q2[4];
#pragma unroll
            for (int jp = 0; jp < 4; jp++) {
                p2[jp].f = *(const float2*)&Ps[f][ty * 8 + jp * 2];
                q2[jp].f = *(const float2*)&Qs[f][ty * 8 + jp * 2];
            }
            float4 wa = *(const float4*)&Was[f][tx * 4];
            float4 wb = *(const float4*)&Wbs[f][tx * 4];
            F2 wpa[4] = {bcast2(wa.x), bcast2(wa.y), bcast2(wa.z), bcast2(wa.w)};
            F2 wpb[4] = {bcast2(wb.x), bcast2(wb.y), bcast2(wb.z), bcast2(wb.w)};
#pragma unroll
            for (int jp = 0; jp < 4; jp++)
#pragma unroll
                for (int u = 0; u < 4; u++) {
                    ffma2(acc[jp][u], p2[jp], wpa[u]);
                    ffma2(acc[jp][u], q2[jp], wpb[u]);
                }
        }
        __syncthreads();
    }
    // epilogue: struct features + bias + relu + w2 contraction + sigmoid
    float B2v = B2[0];
#pragma unroll
    for (int j = 0; j < 8; j++) {
        int e = ty * 8 + j;
        int jp = j >> 1;
        int hi = j & 1;
        float s0 = s0s[e], s1 = s1s[e];
        float sum = 0.f;
#pragma unroll
        for (int u4 = 0; u4 < 4; u4++) {
            int u = tx * 4 + u4;
            float a = hi ? acc[jp][u4].f.y : acc[jp][u4].f.x;
            float v = a + s0 * Wg0[u] + s1 * Wg1[u] + b1s[u];
            v = fmaxf(v, 0.f);
            sum += v * w2s[u];
        }
#pragma unroll
        for (int off = 8; off; off >>= 1)
            sum += __shfl_down_sync(0xffffffffu, sum, off, 16);
        if (tx == 0) {
            float wr = sum + B2v;
            g_w[e0 + e] = W_MAXC / (1.f + expf(-wr));
        }
    }
}

// ------------------- init m = softmax(log_phi[src]) over all E edges ----------
__global__ void init_m_k(const int* __restrict__ srcAll) {
    int e = blockIdx.x * blockDim.x + threadIdx.x;
    if (e >= EEC) return;
    int s = srcAll[e];
    float4 A = *(const float4*)(g_logphi + s * 8);
    float4 Bv = *(const float4*)(g_logphi + s * 8 + 4);
    float lp[8] = {A.x, A.y, A.z, A.w, Bv.x, Bv.y, Bv.z, Bv.w};
    float mx = -1e30f;
#pragma unroll
    for (int c = 0; c < 8; c++) mx = fmaxf(mx, lp[c]);
    float ex[8], sm = 0.f;
#pragma unroll
    for (int c = 0; c < 8; c++) { ex[c] = expf(lp[c] - mx); sm += ex[c]; }
    float inv = 1.f / sm;
    *(float4*)(g_m + (size_t)e * 8)     = make_float4(ex[0]*inv, ex[1]*inv, ex[2]*inv, ex[3]*inv);
    *(float4*)(g_m + (size_t)e * 8 + 4) = make_float4(ex[4]*inv, ex[5]*inv, ex[6]*inv, ex[7]*inv);
}

// ------------------- helpers for BP ------------------------------------------
__device__ __forceinline__ void load8(const float* p, float* r) {
    float4 v0 = *(const float4*)p;
    float4 v1 = *(const float4*)(p + 4);
    r[0]=v0.x; r[1]=v0.y; r[2]=v0.z; r[3]=v0.w;
    r[4]=v1.x; r[5]=v1.y; r[6]=v1.z; r[7]=v1.w;
}
__device__ __forceinline__ void store8(float* p, const float* r) {
    *(float4*)p       = make_float4(r[0], r[1], r[2], r[3]);
    *(float4*)(p + 4) = make_float4(r[4], r[5], r[6], r[7]);
}
__device__ __forceinline__ void upd_m(float* mrow, const float* lp, const float* si,
                                      const float* lf_rev, float alpha) {
    float t[8], mx = -1e30f;
#pragma unroll
    for (int c = 0; c < 8; c++) { t[c] = lp[c] + alpha * (si[c] - lf_rev[c]); mx = fmaxf(mx, t[c]); }
    float ex[8], sm = 0.f;
#pragma unroll
    for (int c = 0; c < 8; c++) { ex[c] = __expf(t[c] - mx); sm += ex[c]; }
    float inv = 1.f / sm;
    float m[8], tot = 0.f;
#pragma unroll
    for (int c = 0; c < 8; c++) {
        m[c] = (1.f - ETA_C) * mrow[c] + ETA_C * (ex[c] * inv);
        m[c] = fmaxf(m[c], EPS_C);
        tot += m[c];
    }
    float it = 1.f / tot;
#pragma unroll
    for (int c = 0; c < 8; c++) mrow[c] = m[c] * it;
}
// compute lf = log(max(m K, eps)) * en for one direction, given Rs in shared
__device__ __forceinline__ void msg_lf(const float* m, float w, float en,
                                       const float* Rs, float* lf) {
    float f[8];
#pragma unroll
    for (int c = 0; c < 8; c++) f[c] = 0.f;
#pragma unroll
    for (int c = 0; c < 8; c++) {
        float mc = m[c];
#pragma unroll
        for (int d = 0; d < 8; d++)
            f[d] += mc * __expf(w * Rs[c * 8 + d]);
    }
#pragma unroll
    for (int c = 0; c < 8; c++)
        lf[c] = __logf(fmaxf(f[c], EPS_C)) * en;
}

// ------------------- first half-iteration: lf & sum from current m ------------
__global__ __launch_bounds__(256) void iterA_k(const int* __restrict__ src,
                                               const int* __restrict__ dst,
                                               float* __restrict__ sum_w) {
    __shared__ float Rs[64];
    if (threadIdx.x < 64) Rs[threadIdx.x] = g_Rs[threadIdx.x];
    __syncthreads();
    int e = blockIdx.x * blockDim.x + threadIdx.x;
    if (e >= E2C) return;
    float w = g_w[e], en = g_en[e];
    int s = src[e], d = dst[e];
    float m1[8], m2[8], lf1[8], lf2[8];
    load8(g_m + (size_t)e * 8, m1);
    load8(g_m + (size_t)(e + E2C) * 8, m2);
    msg_lf(m1, w, en, Rs, lf1);
    msg_lf(m2, w, en, Rs, lf2);
    store8(g_lf + (size_t)e * 8, lf1);
    store8(g_lf + (size_t)(e + E2C) * 8, lf2);
#pragma unroll
    for (int c = 0; c < 8; c++) {
        atomicAdd(&sum_w[d * 8 + c], lf1[c]);
        atomicAdd(&sum_w[s * 8 + c], lf2[c]);
    }
}

// ------------------- fused BP iteration (update m, then new lf & sum) ---------
__global__ __launch_bounds__(256) void fused_k(const int* __restrict__ src,
                                               const int* __restrict__ dst,
                                               const float* __restrict__ sum_r,
                                               float* __restrict__ sum_w) {
    __shared__ float Rs[64];
    if (threadIdx.x < 64) Rs[threadIdx.x] = g_Rs[threadIdx.x];
    __syncthreads();
    int e = blockIdx.x * blockDim.x + threadIdx.x;
    if (e >= E2C) return;
    float alpha = g_alpha;
    int s = src[e], d = dst[e];
    float lf1[8], lf2[8];
    load8(g_lf + (size_t)e * 8, lf1);
    load8(g_lf + (size_t)(e + E2C) * 8, lf2);
    // dir1: edge e (s->d): excl = sum_in[s] - lf[rev] = sum_r[s] - lf2
    {
        float m1[8], lps[8], sis[8];
        load8(g_m + (size_t)e * 8, m1);
        load8(g_logphi + s * 8, lps);
        load8(sum_r + s * 8, sis);
        upd_m(m1, lps, sis, lf2, alpha);
        store8(g_m + (size_t)e * 8, m1);
        float w = g_w[e], en = g_en[e];
        float nlf[8];
        msg_lf(m1, w, en, Rs, nlf);
        store8(g_lf + (size_t)e * 8, nlf);
#pragma unroll
        for (int c = 0; c < 8; c++) atomicAdd(&sum_w[d * 8 + c], nlf[c]);
    }
    // dir2: edge e+E2 (d->s): excl = sum_r[d] - lf1
    {
        float m2[8], lpd[8], sid[8];
        load8(g_m + (size_t)(e + E2C) * 8, m2);
        load8(g_logphi + d * 8, lpd);
        load8(sum_r + d * 8, sid);
        upd_m(m2, lpd, sid, lf1, alpha);
        store8(g_m + (size_t)(e + E2C) * 8, m2);
        float w = g_w[e], en = g_en[e];
        float nlf[8];
        msg_lf(m2, w, en, Rs, nlf);
        store8(g_lf + (size_t)(e + E2C) * 8, nlf);
#pragma unroll
        for (int c = 0; c < 8; c++) atomicAdd(&sum_w[s * 8 + c], nlf[c]);
    }
}

// ------------------- final beliefs -------------------------------------------
__global__ void beliefs_k(const float* __restrict__ sum_r, float* __restrict__ out) {
    int n = blockIdx.x * blockDim.x + threadIdx.x;
    if (n >= NN) return;
    float alpha = g_alpha;
    float lp[8], si[8];
    load8(g_logphi + n * 8, lp);
    load8(sum_r + n * 8, si);
    float t[8], mx = -1e30f;
#pragma unroll
    for (int c = 0; c < 8; c++) { t[c] = lp[c] + alpha * si[c]; mx = fmaxf(mx, t[c]); }
    float ex[8], sm = 0.f;
#pragma unroll
    for (int c = 0; c < 8; c++) { ex[c] = expf(t[c] - mx); sm += ex[c]; }
    float inv = 1.f / sm;
    float o[8];
#pragma unroll
    for (int c = 0; c < 8; c++) o[c] = ex[c] * inv;
    store8(out + (size_t)n * 8, o);
}

// ------------------- launcher -------------------------------------------------
extern "C" void kernel_launch(void* const* d_in, const int* in_sizes, int n_in,
                              void* d_out, int out_size) {
    const float* x      = (const float*)d_in[0];
    const int*   ei     = (const int*)  d_in[1];   // [2, E] : row0 src, row1 dst
    const float* enc_w1 = (const float*)d_in[3];
    const float* enc_b1 = (const float*)d_in[4];
    const float* enc_w2 = (const float*)d_in[5];
    const float* enc_b2 = (const float*)d_in[6];
    const float* edge_w1= (const float*)d_in[7];
    const float* edge_b1= (const float*)d_in[8];
    const float* edge_w2= (const float*)d_in[9];
    const float* edge_b2= (const float*)d_in[10];
    const float* R_raw  = (const float*)d_in[11];
    const float* rsl    = (const float*)d_in[12];
    const float* msg    = (const float*)d_in[13];
    float* out = (float*)d_out;

    const int* src = ei;         // first E2 entries of row0 are unique-edge srcs
    const int* dst = ei + EEC;   // row1

    float* sumA; cudaGetSymbolAddress((void**)&sumA, g_sumA);
    float* sumB; cudaGetSymbolAddress((void**)&sumB, g_sumB);
    float* degp; cudaGetSymbolAddress((void**)&degp, g_deg);

    prep_R_k<<<1, 64>>>(R_raw, rsl, msg);
    enc_gemm_k<<<dim3((NN + 127) / 128, HID / 64), 256>>>(x, enc_w1, enc_b1);
    logits_k<<<(NN * 32 + 255) / 256, 256>>>(enc_w2, enc_b2);
    zero4_k<<<(NN / 4 + 255) / 256, 256>>>((float4*)degp, NN / 4);
    deg_k<<<(E2C + 255) / 256, 256>>>(src, dst);
    logdeg_k<<<(NN + 255) / 256, 256>>>();
    edge_mlp_k<<<E2C / 128, 256>>>(src, dst, edge_w1, edge_b1, edge_w2, edge_b2);
    init_m_k<<<(EEC + 255) / 256, 256>>>(src);  // row0 spans all E directed edges

    const int NC4 = NN * CC / 4;
    zero4_k<<<(NC4 + 255) / 256, 256>>>((float4*)sumA, NC4);
    iterA_k<<<(E2C + 255) / 256, 256>>>(src, dst, sumA);

    float* cur = sumA;
    float* nxt = sumB;
    for (int t = 0; t < T_ITERS; t++) {
        zero4_k<<<(NC4 + 255) / 256, 256>>>((float4*)nxt, NC4);
        fused_k<<<(E2C + 255) / 256, 256>>>(src, dst, cur, nxt);
        float* tmp = cur; cur = nxt; nxt = tmp;
    }
    beliefs_k<<<(NN + 255) / 256, 256>>>(cur, out);
}